// round 10
// baseline (speedup 1.0000x reference)
#include <cuda_runtime.h>

#define F_DIM 513
#define T_DIM 256
#define C_DIM 8
#define N_DIM 4
#define TF (T_DIM * F_DIM)        // 131328
#define NF (N_DIM * F_DIM)        // 2052
#define DIAG_LOAD 7.0710678118654755e-4f  // 0.001/sqrt(2)

// FINAL covariances (already /T): [input(2)][n(4)][entry(64)][f(513)]
// entry 0..7 = diag (real), 8..35 = off-diag re (kk order), 36..63 = off-diag im
__device__ float g_cov[2 * N_DIM * 64 * F_DIM];
// conj(W): [n][c][{re,im}][f]
__device__ float g_wc[N_DIM * C_DIM * 2 * F_DIM];

// -------------------------------------------------------------------------
// Pass 1 (fused): full covariance per (inp,n,f) in ONE block.
// Block 512 = 32 f x 16 t-slices (16 t each). Fully-unrolled t-loop with
// plain loads at the top — ptxas software-pipelines across iterations
// (no manual prefetch buffer, ~16 regs freed for scheduling).
// Then 4 batches of 16 entries reduced across slices via smem; /T store.
// grid (17, 8) = 136 blocks, 1 block/SM, single wave.
// -------------------------------------------------------------------------
__global__ __launch_bounds__(512, 1) void cov_fused_kernel(
    const float* __restrict__ target, const float* __restrict__ noise)
{
    int fx = threadIdx.x & 31;          // f within block
    int sl = threadIdx.x >> 5;          // t-slice 0..15
    int gf = blockIdx.x * 32 + fx;
    int fc = min(gf, F_DIM - 1);
    int inp = blockIdx.y & 1;
    int n   = blockIdx.y >> 1;
    const float* src = inp ? noise : target;
    int t0 = sl * 16;

    float d[8], orr[28], oii[28];
#pragma unroll
    for (int i = 0; i < 8; i++) d[i] = 0.f;
#pragma unroll
    for (int i = 0; i < 28; i++) { orr[i] = 0.f; oii[i] = 0.f; }

    // layout (N, 2, C, T, F): plane v = ri*8+c has stride TF
    const float* base = src + (size_t)(16 * n) * TF + fc + (size_t)t0 * F_DIM;

#pragma unroll
    for (int tt = 0; tt < 16; ++tt) {
        const float* p = base + (size_t)tt * F_DIM;
        float x[16];
#pragma unroll
        for (int v = 0; v < 16; v++)
            x[v] = __ldg(p + (size_t)v * TF);
        // xr = x[0..7], xi = x[8..15]
#pragma unroll
        for (int i = 0; i < 8; i++)
            d[i] = fmaf(x[i], x[i], fmaf(x[8 + i], x[8 + i], d[i]));
        int k = 0;
#pragma unroll
        for (int i = 0; i < 8; i++)
#pragma unroll
            for (int j = i + 1; j < 8; j++) {
                orr[k] = fmaf(x[i], x[j], fmaf(x[8 + i], x[8 + j], orr[k]));
                oii[k] = fmaf(x[8 + i], x[j], fmaf(-x[i], x[8 + j], oii[k]));
                k++;
            }
    }

    // Cross-slice reduction, 4 batches of 16 entries. smem 32 KB.
    __shared__ float sred[16][16][32];   // [entry-in-batch][slice][f]
    float* gout = g_cov + (size_t)(inp * N_DIM + n) * 64 * F_DIM;
    const float invT = 1.0f / (float)T_DIM;

#pragma unroll
    for (int b = 0; b < 4; b++) {
#pragma unroll
        for (int q = 0; q < 16; q++) {
            int e = b * 16 + q;          // compile-time
            float v = (e < 8) ? d[e] : (e < 36 ? orr[e - 8] : oii[e - 36]);
            sred[q][sl][fx] = v;
        }
        __syncthreads();
        {
            int q = sl;                  // each thread one (e, f) output
            float sv = 0.f;
#pragma unroll
            for (int s = 0; s < 16; s++) sv += sred[q][s][fx];
            if (gf < F_DIM)
                gout[(size_t)(b * 16 + q) * F_DIM + gf] = sv * invT;
        }
        __syncthreads();
    }
}

// -------------------------------------------------------------------------
// Pass 2: per-(n,f) solve. Block = 256 thr = 8 matrices -> 257 blocks.
// Covariances are final; staging is one coalesced load per entry.
// Solve phase: threads 0..63 (8 matrices x 8 lanes), complex Gauss-Jordan.
// -------------------------------------------------------------------------
__global__ __launch_bounds__(256) void solve_kernel(const int* __restrict__ ref_idx)
{
    __shared__ float s_cov[2][64][9];    // [input][entry][matrix + pad]
    int tid = threadIdx.x;
    int m0  = blockIdx.x * 8;

#pragma unroll
    for (int r = 0; r < 4; r++) {
        int o  = r * 256 + tid;
        int mi = o & 7;
        int e  = (o >> 3) & 63;
        int ip = o >> 9;
        int m  = min(m0 + mi, NF - 1);
        int n  = m / F_DIM, f = m % F_DIM;
        s_cov[ip][e][mi] =
            g_cov[((size_t)(ip * N_DIM + n) * 64 + e) * F_DIM + f];
    }
    __syncthreads();

    if (tid >= 64) return;
    int mi = tid >> 3;
    int i  = tid & 7;
    int m  = min(m0 + mi, NF - 1);
    int n  = m / F_DIM, f = m % F_DIM;
    const unsigned FULL = 0xffffffffu;

    float nr[8], ni[8];
#pragma unroll
    for (int j = 0; j < 8; j++) {
        if (j == i) { nr[j] = s_cov[1][i][mi] + DIAG_LOAD; ni[j] = DIAG_LOAD; }
        else {
            int a = min(i, j), b = max(i, j);
            int kk = 7 * a - (a * (a - 1)) / 2 + (b - a - 1);
            float sign = (i < j) ? 1.f : -1.f;
            nr[j] = s_cov[1][8 + kk][mi];
            ni[j] = sign * s_cov[1][36 + kk][mi];
        }
    }

#pragma unroll
    for (int kp = 0; kp < 8; kp++) {
        float akk_r = __shfl_sync(FULL, nr[kp], kp, 8);
        float akk_i = __shfl_sync(FULL, ni[kp], kp, 8);
        float idn = 1.0f / fmaf(akk_r, akk_r, akk_i * akk_i);
        float p_r = akk_r * idn, p_i = -akk_i * idn;
        float s_r[8], s_i[8];
#pragma unroll
        for (int j = 0; j < 8; j++) {
            float ar = __shfl_sync(FULL, nr[j], kp, 8);
            float ai = __shfl_sync(FULL, ni[j], kp, 8);
            s_r[j] = ar * p_r - ai * p_i;
            s_i[j] = ar * p_i + ai * p_r;
        }
        if (i == kp) {
#pragma unroll
            for (int j = 0; j < 8; j++) { nr[j] = s_r[j]; ni[j] = s_i[j]; }
            nr[kp] = p_r; ni[kp] = p_i;
        } else {
            float f_r = nr[kp], f_i = ni[kp];
#pragma unroll
            for (int j = 0; j < 8; j++) {
                if (j == kp) continue;
                nr[j] -= f_r * s_r[j] - f_i * s_i[j];
                ni[j] -= f_r * s_i[j] + f_i * s_r[j];
            }
            nr[kp] = -(f_r * p_r - f_i * p_i);
            ni[kp] = -(f_r * p_i + f_i * p_r);
        }
    }

    float tr_[8], ti[8];
#pragma unroll
    for (int j = 0; j < 8; j++) {
        if (j == i) { tr_[j] = s_cov[0][i][mi]; ti[j] = 0.f; }
        else {
            int a = min(i, j), b = max(i, j);
            int kk = 7 * a - (a * (a - 1)) / 2 + (b - a - 1);
            float sign = (i < j) ? 1.f : -1.f;
            tr_[j] = s_cov[0][8 + kk][mi];
            ti[j]  = sign * s_cov[0][36 + kk][mi];
        }
    }

    float trc_r = 0.f, trc_i = 0.f;
#pragma unroll
    for (int j = 0; j < 8; j++) {
        trc_r += nr[j] * tr_[j] + ni[j] * ti[j];
        trc_i += ni[j] * tr_[j] - nr[j] * ti[j];
    }
#pragma unroll
    for (int off = 4; off > 0; off >>= 1) {
        trc_r += __shfl_xor_sync(FULL, trc_r, off, 8);
        trc_i += __shfl_xor_sync(FULL, trc_i, off, 8);
    }

    int ref = *ref_idx;
    float pr = 0.f, pi = 0.f;
#pragma unroll
    for (int jj = 0; jj < 8; jj++)
        if (jj == ref) { pr = tr_[jj]; pi = ti[jj]; }

    float w_r = 0.f, w_i = 0.f;
#pragma unroll
    for (int j = 0; j < 8; j++) {
        float br = __shfl_sync(FULL, pr, j, 8);
        float bi = __shfl_sync(FULL, pi, j, 8);
        w_r += nr[j] * br - ni[j] * bi;
        w_i += nr[j] * bi + ni[j] * br;
    }

    float ldn = 1.0f / fmaf(trc_r, trc_r, trc_i * trc_i);
    float lr = trc_r * ldn, li = -trc_i * ldn;
    float Wr = w_r * lr - w_i * li;
    float Wi = w_r * li + w_i * lr;

    g_wc[((n * 8 + i) * 2 + 0) * F_DIM + f] = Wr;
    g_wc[((n * 8 + i) * 2 + 1) * F_DIM + f] = -Wi;
}

// -------------------------------------------------------------------------
// Pass 3: beamform, 4 t's per thread, all 64 loads hoisted (MLP=64).
// grid (5, 64, 4) = 1280 blocks of 128.
// -------------------------------------------------------------------------
#define TPER 4
__global__ __launch_bounds__(128) void beamform_kernel(
    const float* __restrict__ mix, float* __restrict__ out)
{
    int f = blockIdx.x * blockDim.x + threadIdx.x;
    if (f >= F_DIM) return;
    int n  = blockIdx.z;
    int t0 = blockIdx.y * TPER;

    float wr[8], wi[8];
#pragma unroll
    for (int c = 0; c < 8; c++) {
        wr[c] = g_wc[((n * 8 + c) * 2 + 0) * F_DIM + f];
        wi[c] = g_wc[((n * 8 + c) * 2 + 1) * F_DIM + f];
    }

    const float* baseR = mix + (size_t)(16 * n) * TF + f;
    const float* baseI = mix + (size_t)(16 * n + 8) * TF + f;
    float* outR = out + (size_t)(2 * n) * TF + f;      // (N,2,1,T,F)
    float* outI = out + (size_t)(2 * n + 1) * TF + f;

    float yr[TPER][8], yi[TPER][8];
#pragma unroll
    for (int dt = 0; dt < TPER; dt++) {
        int off = (t0 + dt) * F_DIM;
#pragma unroll
        for (int c = 0; c < 8; c++) {
            yr[dt][c] = __ldg(baseR + (size_t)c * TF + off);
            yi[dt][c] = __ldg(baseI + (size_t)c * TF + off);
        }
    }
#pragma unroll
    for (int dt = 0; dt < TPER; dt++) {
        float Xr = 0.f, Xi = 0.f;
#pragma unroll
        for (int c = 0; c < 8; c++) {
            Xr += wr[c] * yr[dt][c] - wi[c] * yi[dt][c];
            Xi += wr[c] * yi[dt][c] + wi[c] * yr[dt][c];
        }
        int off = (t0 + dt) * F_DIM;
        outR[off] = Xr;
        outI[off] = Xi;
    }
}

// -------------------------------------------------------------------------
extern "C" void kernel_launch(void* const* d_in, const int* in_sizes, int n_in,
                              void* d_out, int out_size)
{
    const float* mixture = (const float*)d_in[0];
    const float* target  = (const float*)d_in[1];
    const float* noise   = (const float*)d_in[2];
    const int*   ref     = (const int*)d_in[3];
    float* out = (float*)d_out;

    dim3 g1((F_DIM + 31) / 32, N_DIM * 2);   // 17 x 8 = 136 blocks
    cov_fused_kernel<<<g1, 512>>>(target, noise);

    int groups = (NF + 7) / 8;                // 257 blocks
    solve_kernel<<<groups, 256>>>(ref);

    dim3 g3((F_DIM + 127) / 128, T_DIM / TPER, N_DIM);
    beamform_kernel<<<g3, 128>>>(mixture, out);
}

// round 11
// speedup vs baseline: 1.0873x; 1.0873x over previous
#include <cuda_runtime.h>

#define F_DIM 513
#define T_DIM 256
#define C_DIM 8
#define N_DIM 4
#define TF (T_DIM * F_DIM)        // 131328
#define NF (N_DIM * F_DIM)        // 2052
#define DIAG_LOAD 7.0710678118654755e-4f  // 0.001/sqrt(2)

// FINAL covariances (already /T): [input(2)][n(4)][entry(64)][f(513)]
// entry 0..7 = diag (real), 8..35 = off-diag re (kk order), 36..63 = off-diag im
__device__ float g_cov[2 * N_DIM * 64 * F_DIM];
// conj(W): [n][c][{re,im}][f]
__device__ float g_wc[N_DIM * C_DIM * 2 * F_DIM];

// ---- packed fp32x2 helpers (FFMA2 is PTX-only; ptxas never emits it) ----
__device__ __forceinline__ unsigned long long pack2(float lo, float hi) {
    unsigned long long r;
    asm("mov.b64 %0, {%1, %2};" : "=l"(r) : "f"(lo), "f"(hi));
    return r;
}
__device__ __forceinline__ void fma2(unsigned long long& acc,
                                     unsigned long long a, unsigned long long b) {
    asm("fma.rn.f32x2 %0, %1, %2, %0;" : "+l"(acc) : "l"(a), "l"(b));
}
__device__ __forceinline__ void unpack2(unsigned long long v, float& lo, float& hi) {
    asm("mov.b64 {%0, %1}, %2;" : "=f"(lo), "=f"(hi) : "l"(v));
}

// -------------------------------------------------------------------------
// Pass 1 (fused): full covariance per (inp,n,f) in ONE block.
// Block 512 = 32 f x 16 t-slices (16 t each). Off-diag entry (re,im) lives
// in one 64-bit f32x2 accumulator: 2 FFMA2 per entry per t (vs 4 scalar).
//   acc.lo += xr_i*xr_j + xi_i*xi_j      (P=(xr_i,xi_i) * BR=(xr_j,xr_j);
//   acc.hi += xi_i*xr_j - xr_i*xi_j       Q=(xi_i,-xr_i) * BI=(xi_j,xi_j))
// Diag: dd_c += (xr^2, xi^2) via 1 FFMA2, lane-summed at the end.
// Then 4 batches of 16 entries reduced across slices via smem; /T store.
// grid (17, 8) = 136 blocks, 1 block/SM, single wave.
// -------------------------------------------------------------------------
__global__ __launch_bounds__(512, 1) void cov_fused_kernel(
    const float* __restrict__ target, const float* __restrict__ noise)
{
    int fx = threadIdx.x & 31;          // f within block
    int sl = threadIdx.x >> 5;          // t-slice 0..15
    int gf = blockIdx.x * 32 + fx;
    int fc = min(gf, F_DIM - 1);
    int inp = blockIdx.y & 1;
    int n   = blockIdx.y >> 1;
    const float* src = inp ? noise : target;
    int t0 = sl * 16;

    unsigned long long acc[28], dd[8];
#pragma unroll
    for (int k = 0; k < 28; k++) acc[k] = 0ull;
#pragma unroll
    for (int c = 0; c < 8; c++) dd[c] = 0ull;

    // layout (N, 2, C, T, F): plane v = ri*8+c has stride TF
    const float* base = src + (size_t)(16 * n) * TF + fc + (size_t)t0 * F_DIM;

#pragma unroll
    for (int tt = 0; tt < 16; ++tt) {
        const float* p = base + (size_t)tt * F_DIM;
        float x[16];
#pragma unroll
        for (int v = 0; v < 16; v++)
            x[v] = __ldg(p + (size_t)v * TF);

        unsigned long long P[8], Q[8];
#pragma unroll
        for (int c = 0; c < 8; c++) {
            P[c] = pack2(x[c], x[8 + c]);
            Q[c] = pack2(x[8 + c], -x[c]);
            fma2(dd[c], P[c], P[c]);
        }
#pragma unroll
        for (int j = 1; j < 8; j++) {
            unsigned long long BR = pack2(x[j], x[j]);
            unsigned long long BI = pack2(x[8 + j], x[8 + j]);
#pragma unroll
            for (int i = 0; i < j; i++) {
                int kk = 7 * i - (i * (i - 1)) / 2 + (j - i - 1);
                fma2(acc[kk], P[i], BR);
                fma2(acc[kk], Q[i], BI);
            }
        }
    }

    // Unpack to the entry layout
    float d[8], orr[28], oii[28];
#pragma unroll
    for (int c = 0; c < 8; c++) {
        float a, b; unpack2(dd[c], a, b); d[c] = a + b;
    }
#pragma unroll
    for (int k = 0; k < 28; k++) unpack2(acc[k], orr[k], oii[k]);

    // Cross-slice reduction, 4 batches of 16 entries. smem 32 KB.
    __shared__ float sred[16][16][32];   // [entry-in-batch][slice][f]
    float* gout = g_cov + (size_t)(inp * N_DIM + n) * 64 * F_DIM;
    const float invT = 1.0f / (float)T_DIM;

#pragma unroll
    for (int b = 0; b < 4; b++) {
#pragma unroll
        for (int q = 0; q < 16; q++) {
            int e = b * 16 + q;          // compile-time
            float v = (e < 8) ? d[e] : (e < 36 ? orr[e - 8] : oii[e - 36]);
            sred[q][sl][fx] = v;
        }
        __syncthreads();
        {
            int q = sl;                  // each thread one (e, f) output
            float sv = 0.f;
#pragma unroll
            for (int s = 0; s < 16; s++) sv += sred[q][s][fx];
            if (gf < F_DIM)
                gout[(size_t)(b * 16 + q) * F_DIM + gf] = sv * invT;
        }
        __syncthreads();
    }
}

// -------------------------------------------------------------------------
// Pass 2: per-(n,f) solve. Block = 256 thr = 8 matrices -> 257 blocks.
// -------------------------------------------------------------------------
__global__ __launch_bounds__(256) void solve_kernel(const int* __restrict__ ref_idx)
{
    __shared__ float s_cov[2][64][9];    // [input][entry][matrix + pad]
    int tid = threadIdx.x;
    int m0  = blockIdx.x * 8;

#pragma unroll
    for (int r = 0; r < 4; r++) {
        int o  = r * 256 + tid;
        int mi = o & 7;
        int e  = (o >> 3) & 63;
        int ip = o >> 9;
        int m  = min(m0 + mi, NF - 1);
        int n  = m / F_DIM, f = m % F_DIM;
        s_cov[ip][e][mi] =
            g_cov[((size_t)(ip * N_DIM + n) * 64 + e) * F_DIM + f];
    }
    __syncthreads();

    if (tid >= 64) return;
    int mi = tid >> 3;
    int i  = tid & 7;
    int m  = min(m0 + mi, NF - 1);
    int n  = m / F_DIM, f = m % F_DIM;
    const unsigned FULL = 0xffffffffu;

    float nr[8], ni[8];
#pragma unroll
    for (int j = 0; j < 8; j++) {
        if (j == i) { nr[j] = s_cov[1][i][mi] + DIAG_LOAD; ni[j] = DIAG_LOAD; }
        else {
            int a = min(i, j), b = max(i, j);
            int kk = 7 * a - (a * (a - 1)) / 2 + (b - a - 1);
            float sign = (i < j) ? 1.f : -1.f;
            nr[j] = s_cov[1][8 + kk][mi];
            ni[j] = sign * s_cov[1][36 + kk][mi];
        }
    }

#pragma unroll
    for (int kp = 0; kp < 8; kp++) {
        float akk_r = __shfl_sync(FULL, nr[kp], kp, 8);
        float akk_i = __shfl_sync(FULL, ni[kp], kp, 8);
        float idn = 1.0f / fmaf(akk_r, akk_r, akk_i * akk_i);
        float p_r = akk_r * idn, p_i = -akk_i * idn;
        float s_r[8], s_i[8];
#pragma unroll
        for (int j = 0; j < 8; j++) {
            float ar = __shfl_sync(FULL, nr[j], kp, 8);
            float ai = __shfl_sync(FULL, ni[j], kp, 8);
            s_r[j] = ar * p_r - ai * p_i;
            s_i[j] = ar * p_i + ai * p_r;
        }
        if (i == kp) {
#pragma unroll
            for (int j = 0; j < 8; j++) { nr[j] = s_r[j]; ni[j] = s_i[j]; }
            nr[kp] = p_r; ni[kp] = p_i;
        } else {
            float f_r = nr[kp], f_i = ni[kp];
#pragma unroll
            for (int j = 0; j < 8; j++) {
                if (j == kp) continue;
                nr[j] -= f_r * s_r[j] - f_i * s_i[j];
                ni[j] -= f_r * s_i[j] + f_i * s_r[j];
            }
            nr[kp] = -(f_r * p_r - f_i * p_i);
            ni[kp] = -(f_r * p_i + f_i * p_r);
        }
    }

    float tr_[8], ti[8];
#pragma unroll
    for (int j = 0; j < 8; j++) {
        if (j == i) { tr_[j] = s_cov[0][i][mi]; ti[j] = 0.f; }
        else {
            int a = min(i, j), b = max(i, j);
            int kk = 7 * a - (a * (a - 1)) / 2 + (b - a - 1);
            float sign = (i < j) ? 1.f : -1.f;
            tr_[j] = s_cov[0][8 + kk][mi];
            ti[j]  = sign * s_cov[0][36 + kk][mi];
        }
    }

    float trc_r = 0.f, trc_i = 0.f;
#pragma unroll
    for (int j = 0; j < 8; j++) {
        trc_r += nr[j] * tr_[j] + ni[j] * ti[j];
        trc_i += ni[j] * tr_[j] - nr[j] * ti[j];
    }
#pragma unroll
    for (int off = 4; off > 0; off >>= 1) {
        trc_r += __shfl_xor_sync(FULL, trc_r, off, 8);
        trc_i += __shfl_xor_sync(FULL, trc_i, off, 8);
    }

    int ref = *ref_idx;
    float pr = 0.f, pi = 0.f;
#pragma unroll
    for (int jj = 0; jj < 8; jj++)
        if (jj == ref) { pr = tr_[jj]; pi = ti[jj]; }

    float w_r = 0.f, w_i = 0.f;
#pragma unroll
    for (int j = 0; j < 8; j++) {
        float br = __shfl_sync(FULL, pr, j, 8);
        float bi = __shfl_sync(FULL, pi, j, 8);
        w_r += nr[j] * br - ni[j] * bi;
        w_i += nr[j] * bi + ni[j] * br;
    }

    float ldn = 1.0f / fmaf(trc_r, trc_r, trc_i * trc_i);
    float lr = trc_r * ldn, li = -trc_i * ldn;
    float Wr = w_r * lr - w_i * li;
    float Wi = w_r * li + w_i * lr;

    g_wc[((n * 8 + i) * 2 + 0) * F_DIM + f] = Wr;
    g_wc[((n * 8 + i) * 2 + 1) * F_DIM + f] = -Wi;
}

// -------------------------------------------------------------------------
// Pass 3: beamform, TPER=2 (best measured), loads hoisted.
// grid (5, 128, 4) = 2560 blocks of 128.
// -------------------------------------------------------------------------
#define TPER 2
__global__ __launch_bounds__(128) void beamform_kernel(
    const float* __restrict__ mix, float* __restrict__ out)
{
    int f = blockIdx.x * blockDim.x + threadIdx.x;
    if (f >= F_DIM) return;
    int n  = blockIdx.z;
    int t0 = blockIdx.y * TPER;

    float wr[8], wi[8];
#pragma unroll
    for (int c = 0; c < 8; c++) {
        wr[c] = g_wc[((n * 8 + c) * 2 + 0) * F_DIM + f];
        wi[c] = g_wc[((n * 8 + c) * 2 + 1) * F_DIM + f];
    }

    const float* baseR = mix + (size_t)(16 * n) * TF + f;
    const float* baseI = mix + (size_t)(16 * n + 8) * TF + f;
    float* outR = out + (size_t)(2 * n) * TF + f;      // (N,2,1,T,F)
    float* outI = out + (size_t)(2 * n + 1) * TF + f;

    float yr[TPER][8], yi[TPER][8];
#pragma unroll
    for (int dt = 0; dt < TPER; dt++) {
        int off = (t0 + dt) * F_DIM;
#pragma unroll
        for (int c = 0; c < 8; c++) {
            yr[dt][c] = __ldg(baseR + (size_t)c * TF + off);
            yi[dt][c] = __ldg(baseI + (size_t)c * TF + off);
        }
    }
#pragma unroll
    for (int dt = 0; dt < TPER; dt++) {
        float Xr = 0.f, Xi = 0.f;
#pragma unroll
        for (int c = 0; c < 8; c++) {
            Xr += wr[c] * yr[dt][c] - wi[c] * yi[dt][c];
            Xi += wr[c] * yi[dt][c] + wi[c] * yr[dt][c];
        }
        int off = (t0 + dt) * F_DIM;
        outR[off] = Xr;
        outI[off] = Xi;
    }
}

// -------------------------------------------------------------------------
extern "C" void kernel_launch(void* const* d_in, const int* in_sizes, int n_in,
                              void* d_out, int out_size)
{
    const float* mixture = (const float*)d_in[0];
    const float* target  = (const float*)d_in[1];
    const float* noise   = (const float*)d_in[2];
    const int*   ref     = (const int*)d_in[3];
    float* out = (float*)d_out;

    dim3 g1((F_DIM + 31) / 32, N_DIM * 2);   // 17 x 8 = 136 blocks
    cov_fused_kernel<<<g1, 512>>>(target, noise);

    int groups = (NF + 7) / 8;                // 257 blocks
    solve_kernel<<<groups, 256>>>(ref);

    dim3 g3((F_DIM + 127) / 128, T_DIM / TPER, N_DIM);
    beamform_kernel<<<g3, 128>>>(mixture, out);
}